// round 1
// baseline (speedup 1.0000x reference)
#include <cuda_runtime.h>
#include <math.h>

#define SEQ 2048
#define DM  1024
#define NH  16
#define HD  64
#define LAT 256

// Scratch (no allocation allowed) — device globals.
__device__ float g_q[SEQ * DM];
__device__ float g_ckv[SEQ * LAT];
__device__ float g_k[SEQ * DM];
__device__ float g_v[SEQ * DM];
__device__ float g_ctx[SEQ * DM];

// ---------------------------------------------------------------------------
// Generic tiled fp32 GEMM: C[M,N] = A[M,K] @ B[K,N] (+ bias), row-major,
// 64x64 tile, BK=16, 256 threads, 4x4 per thread.
// blockIdx.z batches independent GEMMs sharing A (wheel projections):
//   B += z*K*N, bias += z*N, C += z*N.
// ---------------------------------------------------------------------------
__global__ __launch_bounds__(256) void gemm64(
    const float* __restrict__ A, const float* __restrict__ B,
    const float* __restrict__ bias, float* __restrict__ C,
    int M, int N, int K, int lda, int ldb, int ldc)
{
    __shared__ float As[16][65];   // [kk][m], pad 65 -> conflict-free transposed store
    __shared__ float Bs[16][64];   // [kk][n]

    const int tid = threadIdx.x;
    const int tx = tid & 15;       // n-direction
    const int ty = tid >> 4;       // m-direction
    const int m0 = blockIdx.y * 64;
    const int n0 = blockIdx.x * 64;
    const int z  = blockIdx.z;

    B += (long)z * K * N;
    C += (long)z * N;
    const float* bptr = bias ? bias + (long)z * N : nullptr;

    float acc[4][4] = {};

    for (int k0 = 0; k0 < K; k0 += 16) {
        // A tile: 64x16 -> As[kk][m]
        #pragma unroll
        for (int e = 0; e < 4; e++) {
            int idx = e * 256 + tid;
            int m  = idx >> 4;
            int kk = idx & 15;
            As[kk][m] = A[(long)(m0 + m) * lda + k0 + kk];
        }
        // B tile: 16x64 -> Bs[kk][n] (fully coalesced)
        #pragma unroll
        for (int e = 0; e < 4; e++) {
            int idx = e * 256 + tid;
            int kk = idx >> 6;
            int n  = idx & 63;
            Bs[kk][n] = B[(long)(k0 + kk) * ldb + n0 + n];
        }
        __syncthreads();

        #pragma unroll
        for (int kk = 0; kk < 16; kk++) {
            float a[4], b[4];
            #pragma unroll
            for (int i = 0; i < 4; i++) a[i] = As[kk][ty * 4 + i];
            float4 bv = *reinterpret_cast<const float4*>(&Bs[kk][tx * 4]);
            b[0] = bv.x; b[1] = bv.y; b[2] = bv.z; b[3] = bv.w;
            #pragma unroll
            for (int i = 0; i < 4; i++)
                #pragma unroll
                for (int j = 0; j < 4; j++)
                    acc[i][j] += a[i] * b[j];
        }
        __syncthreads();
    }

    #pragma unroll
    for (int i = 0; i < 4; i++) {
        #pragma unroll
        for (int j = 0; j < 4; j++) {
            float val = acc[i][j];
            if (bptr) val += bptr[n0 + tx * 4 + j];
            C[(long)(m0 + ty * 4 + i) * ldc + n0 + tx * 4 + j] = val;
        }
    }
}

// ---------------------------------------------------------------------------
// Flash attention, fp32. One CTA per (64-query tile, head).
// Q/K staged d-major (stride 65, conflict-free transpose), V key-major,
// P staged key-major so the P@V pass is a clean smem GEMM.
// ---------------------------------------------------------------------------
__global__ __launch_bounds__(256) void flash64(
    const float* __restrict__ q, const float* __restrict__ k,
    const float* __restrict__ v, float* __restrict__ ctx)
{
    extern __shared__ float sm[];
    float* Qs = sm;                 // [64 d][65]
    float* Ks = Qs + 64 * 65;       // [64 d][65]
    float* Vs = Ks + 64 * 65;       // [64 key][64 d]
    float* Ps = Vs + 64 * 64;       // [64 key][64 row]

    const int tid = threadIdx.x;
    const int tx = tid & 15;        // key / dim direction
    const int ty = tid >> 4;        // query-row direction
    const int h  = blockIdx.y;
    const int i0 = blockIdx.x * 64;
    const float scale = 0.125f;     // 1/sqrt(64)

    // Load Q tile (pre-scaled), transposed to d-major.
    #pragma unroll
    for (int e = 0; e < 16; e++) {
        int idx = e * 256 + tid;
        int r = idx >> 6;
        int d = idx & 63;
        Qs[d * 65 + r] = q[(long)(i0 + r) * DM + h * HD + d] * scale;
    }

    float m[4], l[4], acc[4][4];
    #pragma unroll
    for (int i = 0; i < 4; i++) {
        m[i] = -INFINITY; l[i] = 0.f;
        #pragma unroll
        for (int j = 0; j < 4; j++) acc[i][j] = 0.f;
    }

    for (int j0 = 0; j0 < SEQ; j0 += 64) {
        __syncthreads();  // protect Ks/Vs/Ps reuse (and Q visibility on iter 0)
        #pragma unroll
        for (int e = 0; e < 16; e++) {
            int idx = e * 256 + tid;
            int r = idx >> 6;
            int d = idx & 63;
            Ks[d * 65 + r] = k[(long)(j0 + r) * DM + h * HD + d];
            Vs[r * 64 + d] = v[(long)(j0 + r) * DM + h * HD + d];
        }
        __syncthreads();

        // S = (Q*scale) @ K^T  -> s[i][j], rows ty*4+i, keys tx*4+j
        float s[4][4] = {};
        #pragma unroll
        for (int d = 0; d < 64; d++) {
            float a[4], b[4];
            #pragma unroll
            for (int i = 0; i < 4; i++) a[i] = Qs[d * 65 + ty * 4 + i];
            #pragma unroll
            for (int j = 0; j < 4; j++) b[j] = Ks[d * 65 + tx * 4 + j];
            #pragma unroll
            for (int i = 0; i < 4; i++)
                #pragma unroll
                for (int j = 0; j < 4; j++)
                    s[i][j] += a[i] * b[j];
        }

        // Online softmax update (row reductions across 16 tx lanes).
        float alpha[4];
        #pragma unroll
        for (int i = 0; i < 4; i++) {
            float rm = fmaxf(fmaxf(s[i][0], s[i][1]), fmaxf(s[i][2], s[i][3]));
            #pragma unroll
            for (int off = 1; off < 16; off <<= 1)
                rm = fmaxf(rm, __shfl_xor_sync(0xffffffffu, rm, off));
            float mn = fmaxf(m[i], rm);
            alpha[i] = __expf(m[i] - mn);
            m[i] = mn;
            float rs = 0.f;
            #pragma unroll
            for (int j = 0; j < 4; j++) { s[i][j] = __expf(s[i][j] - mn); rs += s[i][j]; }
            #pragma unroll
            for (int off = 1; off < 16; off <<= 1)
                rs += __shfl_xor_sync(0xffffffffu, rs, off);
            l[i] = l[i] * alpha[i] + rs;
            #pragma unroll
            for (int j = 0; j < 4; j++) acc[i][j] *= alpha[i];
        }

        // Stage P key-major: Ps[key][row]
        #pragma unroll
        for (int i = 0; i < 4; i++)
            #pragma unroll
            for (int j = 0; j < 4; j++)
                Ps[(tx * 4 + j) * 64 + ty * 4 + i] = s[i][j];
        __syncthreads();

        // O += P @ V  (acc[i][j]: row ty*4+i, dim tx*4+j)
        #pragma unroll
        for (int kk = 0; kk < 64; kk++) {
            float4 pv = *reinterpret_cast<const float4*>(&Ps[kk * 64 + ty * 4]);
            float4 vv = *reinterpret_cast<const float4*>(&Vs[kk * 64 + tx * 4]);
            float p[4] = {pv.x, pv.y, pv.z, pv.w};
            float vb[4] = {vv.x, vv.y, vv.z, vv.w};
            #pragma unroll
            for (int i = 0; i < 4; i++)
                #pragma unroll
                for (int j = 0; j < 4; j++)
                    acc[i][j] += p[i] * vb[j];
        }
    }

    #pragma unroll
    for (int i = 0; i < 4; i++) {
        float inv = 1.0f / l[i];
        #pragma unroll
        for (int j = 0; j < 4; j++)
            ctx[(long)(i0 + ty * 4 + i) * DM + h * HD + tx * 4 + j] = acc[i][j] * inv;
    }
}

// ---------------------------------------------------------------------------
// Launcher
// ---------------------------------------------------------------------------
extern "C" void kernel_launch(void* const* d_in, const int* in_sizes, int n_in,
                              void* d_out, int out_size)
{
    const float* X    = (const float*)d_in[0];  // [2048,1024]
    const float* Wq   = (const float*)d_in[1];  // [1024,1024]
    const float* Wdkv = (const float*)d_in[2];  // [1024,256]
    const float* Wuk  = (const float*)d_in[3];  // [256,1024]
    const float* Wuv  = (const float*)d_in[4];  // [256,1024]
    const float* Wo   = (const float*)d_in[5];  // [1024,1024]
    const float* wW   = (const float*)d_in[6];  // [4,1024,256]
    const float* wb   = (const float*)d_in[7];  // [4,256]
    float* out = (float*)d_out;                 // [2048,2048]

    float *q, *ckv, *kk, *vv, *ctx;
    cudaGetSymbolAddress((void**)&q,   g_q);
    cudaGetSymbolAddress((void**)&ckv, g_ckv);
    cudaGetSymbolAddress((void**)&kk,  g_k);
    cudaGetSymbolAddress((void**)&vv,  g_v);
    cudaGetSymbolAddress((void**)&ctx, g_ctx);

    // q = X @ Wq  [2048,1024]
    gemm64<<<dim3(DM / 64, SEQ / 64, 1), 256>>>(X, Wq, nullptr, q,
                                                SEQ, DM, DM, DM, DM, DM);
    // c_kv = X @ Wdkv  [2048,256]
    gemm64<<<dim3(LAT / 64, SEQ / 64, 1), 256>>>(X, Wdkv, nullptr, ckv,
                                                 SEQ, LAT, DM, DM, LAT, LAT);
    // k = c_kv @ Wuk  [2048,1024]
    gemm64<<<dim3(DM / 64, SEQ / 64, 1), 256>>>(ckv, Wuk, nullptr, kk,
                                                SEQ, DM, LAT, LAT, DM, DM);
    // v = c_kv @ Wuv  [2048,1024]
    gemm64<<<dim3(DM / 64, SEQ / 64, 1), 256>>>(ckv, Wuv, nullptr, vv,
                                                SEQ, DM, LAT, LAT, DM, DM);

    // attention -> ctx [2048,1024]
    const int smem = (64 * 65 * 2 + 64 * 64 * 2) * (int)sizeof(float);  // 66048
    cudaFuncSetAttribute(flash64, cudaFuncAttributeMaxDynamicSharedMemorySize, smem);
    flash64<<<dim3(SEQ / 64, NH, 1), 256, smem>>>(q, kk, vv, ctx);

    // body = ctx @ Wo -> out[:, 0:1024]  (ldc = 2048)
    gemm64<<<dim3(DM / 64, SEQ / 64, 1), 256>>>(ctx, Wo, nullptr, out,
                                                SEQ, DM, DM, DM, DM, 2048);
    // wheels: out[:, 1024 + w*256 + e] = body @ wheel_W[w] + wheel_b[w]
    gemm64<<<dim3(256 / 64, SEQ / 64, 4), 256>>>(out, wW, wb, out + 1024,
                                                 SEQ, 256, DM, 2048, 256, 2048);
}

// round 2
// speedup vs baseline: 2.3149x; 2.3149x over previous
#include <cuda_runtime.h>
#include <math.h>

#define SEQ 2048
#define DM  1024
#define NH  16
#define HD  64
#define LAT 256

// Scratch — device globals (no allocation allowed).
__device__ float g_q[SEQ * DM];
__device__ float g_ckv[SEQ * LAT];
__device__ float g_k[SEQ * DM];
__device__ float g_v[SEQ * DM];
__device__ float g_ctx[SEQ * DM];

// --------------------------------------------------------------------------
// tf32 helpers
// --------------------------------------------------------------------------
__device__ __forceinline__ unsigned f2tf(float x) {
    unsigned r;
    asm("cvt.rna.tf32.f32 %0, %1;" : "=r"(r) : "f"(x));
    return r;
}

__device__ __forceinline__ void mma_tf32(float* c, const unsigned* a, const unsigned* b) {
    asm volatile(
        "mma.sync.aligned.m16n8k8.row.col.f32.tf32.tf32.f32 "
        "{%0,%1,%2,%3}, {%4,%5,%6,%7}, {%8,%9}, {%0,%1,%2,%3};"
        : "+f"(c[0]), "+f"(c[1]), "+f"(c[2]), "+f"(c[3])
        : "r"(a[0]), "r"(a[1]), "r"(a[2]), "r"(a[3]),
          "r"(b[0]), "r"(b[1]));
}

// --------------------------------------------------------------------------
// tf32 tensor-core GEMM: C[M,N] = A[M,K] @ B[K,N] (+bias), row-major.
// CTA tile 128x128, BK=32, 8 warps (4 m x 2 n), warp tile 32x64.
// blockIdx.z batches B/bias/C by z*K*N / z*N / z*N (wheel projections).
// Conflict-free smem: As[m][k] pad 36, Bs[k][n] pad 132.
// --------------------------------------------------------------------------
#define AP 36
#define BP 132
__global__ __launch_bounds__(256) void gemm_tc(
    const float* __restrict__ A, const float* __restrict__ B,
    const float* __restrict__ bias, float* __restrict__ C,
    int M, int N, int K, int lda, int ldb, int ldc)
{
    __shared__ unsigned As[128 * AP];
    __shared__ unsigned Bs[32 * BP];

    const int tid  = threadIdx.x;
    const int lane = tid & 31;
    const int warp = tid >> 5;
    const int g = lane >> 2;      // 0..7
    const int r = lane & 3;       // 0..3
    const int wm = warp & 3;      // 0..3 -> rows wm*32
    const int wn = warp >> 2;     // 0..1 -> cols wn*64

    const int m0 = blockIdx.y * 128;
    const int n0 = blockIdx.x * 128;
    const int z  = blockIdx.z;
    B += (long)z * K * N;
    C += (long)z * N;
    const float* bptr = bias ? bias + (long)z * N : nullptr;

    float acc[2][8][4];
    #pragma unroll
    for (int i = 0; i < 2; i++)
        #pragma unroll
        for (int j = 0; j < 8; j++)
            #pragma unroll
            for (int t = 0; t < 4; t++) acc[i][j][t] = 0.f;

    for (int k0 = 0; k0 < K; k0 += 32) {
        // A tile 128x32 -> As[m][k] (coalesced gmem, conflict-free STS)
        #pragma unroll
        for (int e = 0; e < 16; e++) {
            int idx = e * 256 + tid;
            int m = idx >> 5, kk = idx & 31;
            As[m * AP + kk] = f2tf(A[(long)(m0 + m) * lda + k0 + kk]);
        }
        // B tile 32x128 -> Bs[k][n]
        #pragma unroll
        for (int e = 0; e < 16; e++) {
            int idx = e * 256 + tid;
            int kk = idx >> 7, n = idx & 127;
            Bs[kk * BP + n] = f2tf(B[(long)(k0 + kk) * ldb + n0 + n]);
        }
        __syncthreads();

        #pragma unroll
        for (int ks = 0; ks < 4; ks++) {
            const int k = ks * 8;
            unsigned a[2][4], b[8][2];
            #pragma unroll
            for (int i = 0; i < 2; i++) {
                int row = wm * 32 + i * 16;
                a[i][0] = As[(row + g)     * AP + k + r];
                a[i][1] = As[(row + g + 8) * AP + k + r];
                a[i][2] = As[(row + g)     * AP + k + r + 4];
                a[i][3] = As[(row + g + 8) * AP + k + r + 4];
            }
            #pragma unroll
            for (int j = 0; j < 8; j++) {
                int col = wn * 64 + j * 8;
                b[j][0] = Bs[(k + r)     * BP + col + g];
                b[j][1] = Bs[(k + r + 4) * BP + col + g];
            }
            #pragma unroll
            for (int i = 0; i < 2; i++)
                #pragma unroll
                for (int j = 0; j < 8; j++)
                    mma_tf32(acc[i][j], a[i], b[j]);
        }
        __syncthreads();
    }

    // Epilogue: c0/c1 at (row+g, col+2r), c2/c3 at (row+g+8, col+2r)
    #pragma unroll
    for (int i = 0; i < 2; i++) {
        int row = m0 + wm * 32 + i * 16;
        #pragma unroll
        for (int j = 0; j < 8; j++) {
            int col = n0 + wn * 64 + j * 8 + 2 * r;
            float b0 = 0.f, b1 = 0.f;
            if (bptr) { b0 = bptr[col]; b1 = bptr[col + 1]; }
            float2 v0 = make_float2(acc[i][j][0] + b0, acc[i][j][1] + b1);
            float2 v1 = make_float2(acc[i][j][2] + b0, acc[i][j][3] + b1);
            *reinterpret_cast<float2*>(&C[(long)(row + g)     * ldc + col]) = v0;
            *reinterpret_cast<float2*>(&C[(long)(row + g + 8) * ldc + col]) = v1;
        }
    }
}

// --------------------------------------------------------------------------
// Flash attention with tf32 mma. One CTA = (64-query tile, head).
// 4 warps x 16 rows. Q frags register-resident; S and PV via m16n8k8.
// smem (pad 68, all accesses conflict-free): Ks, Vs, Ps [64][68] tf32 bits.
// --------------------------------------------------------------------------
#define FP 68
__global__ __launch_bounds__(128) void flash_tc(
    const float* __restrict__ q, const float* __restrict__ k,
    const float* __restrict__ v, float* __restrict__ ctx)
{
    extern __shared__ unsigned sm[];
    unsigned* Ks = sm;                 // [64][68]
    unsigned* Vs = Ks + 64 * FP;
    unsigned* Ps = Vs + 64 * FP;

    const int tid  = threadIdx.x;
    const int lane = tid & 31;
    const int warp = tid >> 5;
    const int g = lane >> 2;
    const int r = lane & 3;
    const int qb = warp * 16;          // warp's query-row base (within tile)
    const int h  = blockIdx.y;
    const int i0 = blockIdx.x * 64;

    // Stage Q (scaled) into Ks, extract register A-fragments.
    #pragma unroll
    for (int e = 0; e < 32; e++) {
        int idx = e * 128 + tid;
        int row = idx >> 6, d = idx & 63;
        Ks[row * FP + d] = f2tf(q[(long)(i0 + row) * DM + h * HD + d] * 0.125f);
    }
    __syncthreads();
    unsigned qa[8][4];
    #pragma unroll
    for (int kt = 0; kt < 8; kt++) {
        int kk = kt * 8;
        qa[kt][0] = Ks[(qb + g)     * FP + kk + r];
        qa[kt][1] = Ks[(qb + g + 8) * FP + kk + r];
        qa[kt][2] = Ks[(qb + g)     * FP + kk + r + 4];
        qa[kt][3] = Ks[(qb + g + 8) * FP + kk + r + 4];
    }
    __syncthreads();

    float mrow[2] = {-INFINITY, -INFINITY};
    float lrow[2] = {0.f, 0.f};
    float o[8][4];
    #pragma unroll
    for (int j = 0; j < 8; j++)
        #pragma unroll
        for (int t = 0; t < 4; t++) o[j][t] = 0.f;

    for (int j0 = 0; j0 < SEQ; j0 += 64) {
        // Load K, V tiles (tf32)
        #pragma unroll
        for (int e = 0; e < 32; e++) {
            int idx = e * 128 + tid;
            int row = idx >> 6, d = idx & 63;
            long gidx = (long)(j0 + row) * DM + h * HD + d;
            Ks[row * FP + d] = f2tf(k[gidx]);
            Vs[row * FP + d] = f2tf(v[gidx]);
        }
        __syncthreads();

        // S = Q @ K^T : s[nt] = 16 rows x 8 keys
        float s[8][4];
        #pragma unroll
        for (int nt = 0; nt < 8; nt++)
            #pragma unroll
            for (int t = 0; t < 4; t++) s[nt][t] = 0.f;
        #pragma unroll
        for (int nt = 0; nt < 8; nt++) {
            #pragma unroll
            for (int kt = 0; kt < 8; kt++) {
                unsigned b[2];
                b[0] = Ks[(nt * 8 + g) * FP + kt * 8 + r];
                b[1] = Ks[(nt * 8 + g) * FP + kt * 8 + r + 4];
                mma_tf32(s[nt], qa[kt], b);
            }
        }

        // Online softmax for both row-halves (rows qb+g and qb+g+8).
        #pragma unroll
        for (int half = 0; half < 2; half++) {
            const int c0 = half * 2, c1 = half * 2 + 1;
            float rmax = -INFINITY;
            #pragma unroll
            for (int nt = 0; nt < 8; nt++)
                rmax = fmaxf(rmax, fmaxf(s[nt][c0], s[nt][c1]));
            rmax = fmaxf(rmax, __shfl_xor_sync(0xffffffffu, rmax, 1));
            rmax = fmaxf(rmax, __shfl_xor_sync(0xffffffffu, rmax, 2));
            float mn = fmaxf(mrow[half], rmax);
            float alpha = __expf(mrow[half] - mn);
            mrow[half] = mn;
            float rs = 0.f;
            #pragma unroll
            for (int nt = 0; nt < 8; nt++) {
                float p0 = __expf(s[nt][c0] - mn);
                float p1 = __expf(s[nt][c1] - mn);
                s[nt][c0] = p0; s[nt][c1] = p1;
                rs += p0 + p1;
            }
            rs += __shfl_xor_sync(0xffffffffu, rs, 1);
            rs += __shfl_xor_sync(0xffffffffu, rs, 2);
            lrow[half] = lrow[half] * alpha + rs;
            #pragma unroll
            for (int nt = 0; nt < 8; nt++) {
                o[nt][c0] *= alpha;
                o[nt][c1] *= alpha;
            }
        }

        // Stage P (tf32) to per-warp smem region, re-fragment as A.
        #pragma unroll
        for (int nt = 0; nt < 8; nt++) {
            uint2 p0 = make_uint2(f2tf(s[nt][0]), f2tf(s[nt][1]));
            uint2 p1 = make_uint2(f2tf(s[nt][2]), f2tf(s[nt][3]));
            *reinterpret_cast<uint2*>(&Ps[(qb + g)     * FP + nt * 8 + 2 * r]) = p0;
            *reinterpret_cast<uint2*>(&Ps[(qb + g + 8) * FP + nt * 8 + 2 * r]) = p1;
        }
        __syncwarp();

        unsigned pa[8][4];
        #pragma unroll
        for (int kt = 0; kt < 8; kt++) {
            int kk = kt * 8;
            pa[kt][0] = Ps[(qb + g)     * FP + kk + r];
            pa[kt][1] = Ps[(qb + g + 8) * FP + kk + r];
            pa[kt][2] = Ps[(qb + g)     * FP + kk + r + 4];
            pa[kt][3] = Ps[(qb + g + 8) * FP + kk + r + 4];
        }

        // O += P @ V
        #pragma unroll
        for (int nt = 0; nt < 8; nt++) {
            #pragma unroll
            for (int kt = 0; kt < 8; kt++) {
                unsigned b[2];
                b[0] = Vs[(kt * 8 + r)     * FP + nt * 8 + g];
                b[1] = Vs[(kt * 8 + r + 4) * FP + nt * 8 + g];
                mma_tf32(o[nt], pa[kt], b);
            }
        }
        __syncthreads();   // before K/V overwrite next iter
    }

    // Normalize and write ctx.
    float inv0 = 1.0f / lrow[0], inv1 = 1.0f / lrow[1];
    #pragma unroll
    for (int nt = 0; nt < 8; nt++) {
        int col = h * HD + nt * 8 + 2 * r;
        float2 v0 = make_float2(o[nt][0] * inv0, o[nt][1] * inv0);
        float2 v1 = make_float2(o[nt][2] * inv1, o[nt][3] * inv1);
        *reinterpret_cast<float2*>(&ctx[(long)(i0 + qb + g)     * DM + col]) = v0;
        *reinterpret_cast<float2*>(&ctx[(long)(i0 + qb + g + 8) * DM + col]) = v1;
    }
}

// --------------------------------------------------------------------------
// Launcher
// --------------------------------------------------------------------------
extern "C" void kernel_launch(void* const* d_in, const int* in_sizes, int n_in,
                              void* d_out, int out_size)
{
    const float* X    = (const float*)d_in[0];
    const float* Wq   = (const float*)d_in[1];
    const float* Wdkv = (const float*)d_in[2];
    const float* Wuk  = (const float*)d_in[3];
    const float* Wuv  = (const float*)d_in[4];
    const float* Wo   = (const float*)d_in[5];
    const float* wW   = (const float*)d_in[6];
    const float* wb   = (const float*)d_in[7];
    float* out = (float*)d_out;

    float *q, *ckv, *kk, *vv, *ctx;
    cudaGetSymbolAddress((void**)&q,   g_q);
    cudaGetSymbolAddress((void**)&ckv, g_ckv);
    cudaGetSymbolAddress((void**)&kk,  g_k);
    cudaGetSymbolAddress((void**)&vv,  g_v);
    cudaGetSymbolAddress((void**)&ctx, g_ctx);

    // q = X @ Wq
    gemm_tc<<<dim3(DM / 128, SEQ / 128, 1), 256>>>(X, Wq, nullptr, q,
                                                   SEQ, DM, DM, DM, DM, DM);
    // c_kv = X @ Wdkv
    gemm_tc<<<dim3(LAT / 128, SEQ / 128, 1), 256>>>(X, Wdkv, nullptr, ckv,
                                                    SEQ, LAT, DM, DM, LAT, LAT);
    // k = c_kv @ Wuk
    gemm_tc<<<dim3(DM / 128, SEQ / 128, 1), 256>>>(ckv, Wuk, nullptr, kk,
                                                   SEQ, DM, LAT, LAT, DM, DM);
    // v = c_kv @ Wuv
    gemm_tc<<<dim3(DM / 128, SEQ / 128, 1), 256>>>(ckv, Wuv, nullptr, vv,
                                                   SEQ, DM, LAT, LAT, DM, DM);

    // attention
    const int smem = 3 * 64 * FP * (int)sizeof(unsigned);  // 52224 B
    cudaFuncSetAttribute(flash_tc, cudaFuncAttributeMaxDynamicSharedMemorySize, smem);
    flash_tc<<<dim3(SEQ / 64, NH, 1), 128, smem>>>(q, kk, vv, ctx);

    // body = ctx @ Wo -> out[:, 0:1024]
    gemm_tc<<<dim3(DM / 128, SEQ / 128, 1), 256>>>(ctx, Wo, nullptr, out,
                                                   SEQ, DM, DM, DM, DM, 2048);
    // wheels -> out[:, 1024:2048]
    gemm_tc<<<dim3(256 / 128, SEQ / 128, 4), 256>>>(out, wW, wb, out + 1024,
                                                    SEQ, 256, DM, 2048, 256, 2048);
}

// round 3
// speedup vs baseline: 2.5271x; 1.0917x over previous
#include <cuda_runtime.h>
#include <math.h>

#define SEQ 2048
#define DM  1024
#define NH  16
#define HD  64
#define LAT 256

// Scratch — device globals (no allocation allowed).
__device__ float g_q[SEQ * DM];
__device__ float g_ckv[SEQ * LAT];
__device__ float g_k[SEQ * DM];
__device__ float g_v[SEQ * DM];
__device__ float g_ctx[SEQ * DM];

// --------------------------------------------------------------------------
// tf32 helpers
// --------------------------------------------------------------------------
__device__ __forceinline__ unsigned f2tf(float x) {
    unsigned r;
    asm("cvt.rna.tf32.f32 %0, %1;" : "=r"(r) : "f"(x));
    return r;
}

__device__ __forceinline__ void mma_tf32(float* c, const unsigned* a, const unsigned* b) {
    asm volatile(
        "mma.sync.aligned.m16n8k8.row.col.f32.tf32.tf32.f32 "
        "{%0,%1,%2,%3}, {%4,%5,%6,%7}, {%8,%9}, {%0,%1,%2,%3};"
        : "+f"(c[0]), "+f"(c[1]), "+f"(c[2]), "+f"(c[3])
        : "r"(a[0]), "r"(a[1]), "r"(a[2]), "r"(a[3]),
          "r"(b[0]), "r"(b[1]));
}

// --------------------------------------------------------------------------
// tf32 tensor-core GEMM (unchanged from R2 — proven correct).
// CTA tile 128x128, BK=32, 8 warps (4 m x 2 n), warp tile 32x64.
// --------------------------------------------------------------------------
#define AP 36
#define BP 132
__global__ __launch_bounds__(256) void gemm_tc(
    const float* __restrict__ A, const float* __restrict__ B,
    const float* __restrict__ bias, float* __restrict__ C,
    int M, int N, int K, int lda, int ldb, int ldc)
{
    __shared__ unsigned As[128 * AP];
    __shared__ unsigned Bs[32 * BP];

    const int tid  = threadIdx.x;
    const int lane = tid & 31;
    const int warp = tid >> 5;
    const int g = lane >> 2;
    const int r = lane & 3;
    const int wm = warp & 3;
    const int wn = warp >> 2;

    const int m0 = blockIdx.y * 128;
    const int n0 = blockIdx.x * 128;
    const int z  = blockIdx.z;
    B += (long)z * K * N;
    C += (long)z * N;
    const float* bptr = bias ? bias + (long)z * N : nullptr;

    float acc[2][8][4];
    #pragma unroll
    for (int i = 0; i < 2; i++)
        #pragma unroll
        for (int j = 0; j < 8; j++)
            #pragma unroll
            for (int t = 0; t < 4; t++) acc[i][j][t] = 0.f;

    for (int k0 = 0; k0 < K; k0 += 32) {
        #pragma unroll
        for (int e = 0; e < 16; e++) {
            int idx = e * 256 + tid;
            int m = idx >> 5, kk = idx & 31;
            As[m * AP + kk] = f2tf(A[(long)(m0 + m) * lda + k0 + kk]);
        }
        #pragma unroll
        for (int e = 0; e < 16; e++) {
            int idx = e * 256 + tid;
            int kk = idx >> 7, n = idx & 127;
            Bs[kk * BP + n] = f2tf(B[(long)(k0 + kk) * ldb + n0 + n]);
        }
        __syncthreads();

        #pragma unroll
        for (int ks = 0; ks < 4; ks++) {
            const int k = ks * 8;
            unsigned a[2][4], b[8][2];
            #pragma unroll
            for (int i = 0; i < 2; i++) {
                int row = wm * 32 + i * 16;
                a[i][0] = As[(row + g)     * AP + k + r];
                a[i][1] = As[(row + g + 8) * AP + k + r];
                a[i][2] = As[(row + g)     * AP + k + r + 4];
                a[i][3] = As[(row + g + 8) * AP + k + r + 4];
            }
            #pragma unroll
            for (int j = 0; j < 8; j++) {
                int col = wn * 64 + j * 8;
                b[j][0] = Bs[(k + r)     * BP + col + g];
                b[j][1] = Bs[(k + r + 4) * BP + col + g];
            }
            #pragma unroll
            for (int i = 0; i < 2; i++)
                #pragma unroll
                for (int j = 0; j < 8; j++)
                    mma_tf32(acc[i][j], a[i], b[j]);
        }
        __syncthreads();
    }

    #pragma unroll
    for (int i = 0; i < 2; i++) {
        int row = m0 + wm * 32 + i * 16;
        #pragma unroll
        for (int j = 0; j < 8; j++) {
            int col = n0 + wn * 64 + j * 8 + 2 * r;
            float b0 = 0.f, b1 = 0.f;
            if (bptr) { b0 = bptr[col]; b1 = bptr[col + 1]; }
            float2 v0 = make_float2(acc[i][j][0] + b0, acc[i][j][1] + b1);
            float2 v1 = make_float2(acc[i][j][2] + b0, acc[i][j][3] + b1);
            *reinterpret_cast<float2*>(&C[(long)(row + g)     * ldc + col]) = v0;
            *reinterpret_cast<float2*>(&C[(long)(row + g + 8) * ldc + col]) = v1;
        }
    }
}

// --------------------------------------------------------------------------
// Flash attention v2: fragment-native smem layouts, all MMA operands via
// LDS.128. CTA = (128-query tile, head), 8 warps x 16 rows, 64-key tiles.
//
// KB: K frags. segment(key, c=d&3) holds 16 words d=c,c+4,..,c+60.
//     addr = key*80 + c*20 + j  (words).  Size 64*80 = 5120 w.
// VB: V frags. segment(key, c8=d&7) holds 8 words d=c8,c8+8,..,c8+56.
//     addr = key*104 + c8*12 + j.         Size 64*104 = 6656 w.
// QB: A-frags of Q then P, per warp. addr = w*1344 + row*84 + c*20 + j.
//     Size 8*1344 = 10752 w.  Total 22528 w = 90112 B.
// --------------------------------------------------------------------------
__global__ __launch_bounds__(256) void flash_tc2(
    const float* __restrict__ q, const float* __restrict__ k,
    const float* __restrict__ v, float* __restrict__ ctx)
{
    extern __shared__ unsigned smx[];
    unsigned* KB = smx;              // 5120
    unsigned* VB = smx + 5120;       // 6656
    unsigned* QB = smx + 11776;      // 10752

    const int tid  = threadIdx.x;
    const int lane = tid & 31;
    const int warp = tid >> 5;
    const int g = lane >> 2;         // 0..7
    const int r = lane & 3;          // 0..3
    const int h  = blockIdx.y;
    const int i0 = blockIdx.x * 128;
    const int wbase = warp * 1344;

    // ---- Stage Q (scaled, tf32) into QB fragment layout ----
    #pragma unroll
    for (int e = 0; e < 8; e++) {
        int idx = e * 256 + tid;
        int row = idx >> 4, dq = idx & 15;
        float4 q4 = *reinterpret_cast<const float4*>(
            &q[(long)(i0 + row) * DM + h * HD + dq * 4]);
        unsigned* p = &QB[(row >> 4) * 1344 + (row & 15) * 84 + dq];
        p[0]  = f2tf(q4.x * 0.125f);
        p[20] = f2tf(q4.y * 0.125f);
        p[40] = f2tf(q4.z * 0.125f);
        p[60] = f2tf(q4.w * 0.125f);
    }
    __syncthreads();

    // ---- Extract Q A-fragments (register-resident) ----
    unsigned qa[8][4];
    {
        const uint4* lo4 = reinterpret_cast<const uint4*>(&QB[wbase + g * 84 + r * 20]);
        const uint4* hi4 = reinterpret_cast<const uint4*>(&QB[wbase + (g + 8) * 84 + r * 20]);
        uint4 L[4] = {lo4[0], lo4[1], lo4[2], lo4[3]};
        uint4 H[4] = {hi4[0], hi4[1], hi4[2], hi4[3]};
        const unsigned* lo = reinterpret_cast<const unsigned*>(L);
        const unsigned* hi = reinterpret_cast<const unsigned*>(H);
        #pragma unroll
        for (int kt = 0; kt < 8; kt++) {
            qa[kt][0] = lo[2 * kt];
            qa[kt][1] = hi[2 * kt];
            qa[kt][2] = lo[2 * kt + 1];
            qa[kt][3] = hi[2 * kt + 1];
        }
    }

    float mrow[2] = {-INFINITY, -INFINITY};
    float lrow[2] = {0.f, 0.f};
    float o[8][4];
    #pragma unroll
    for (int j = 0; j < 8; j++)
        #pragma unroll
        for (int t = 0; t < 4; t++) o[j][t] = 0.f;

    for (int j0 = 0; j0 < SEQ; j0 += 64) {
        // ---- Stage K, V tiles into fragment layouts ----
        #pragma unroll
        for (int e = 0; e < 4; e++) {
            int idx = e * 256 + tid;
            int key = idx >> 4, dq = idx & 15;
            long gbase = (long)(j0 + key) * DM + h * HD + dq * 4;
            float4 k4 = *reinterpret_cast<const float4*>(&k[gbase]);
            float4 v4 = *reinterpret_cast<const float4*>(&v[gbase]);
            unsigned* kp = &KB[key * 80 + dq];
            kp[0]  = f2tf(k4.x);
            kp[20] = f2tf(k4.y);
            kp[40] = f2tf(k4.z);
            kp[60] = f2tf(k4.w);
            int c8b = (dq & 1) * 4;
            unsigned* vp = &VB[key * 104 + c8b * 12 + (dq >> 1)];
            vp[0]  = f2tf(v4.x);
            vp[12] = f2tf(v4.y);
            vp[24] = f2tf(v4.z);
            vp[36] = f2tf(v4.w);
        }
        __syncthreads();

        // ---- S = Q @ K^T ----
        float s[8][4];
        #pragma unroll
        for (int nt = 0; nt < 8; nt++) {
            #pragma unroll
            for (int t = 0; t < 4; t++) s[nt][t] = 0.f;
            const uint4* kp4 = reinterpret_cast<const uint4*>(
                &KB[(nt * 8 + g) * 80 + r * 20]);
            uint4 W[4] = {kp4[0], kp4[1], kp4[2], kp4[3]};
            const unsigned* w = reinterpret_cast<const unsigned*>(W);
            #pragma unroll
            for (int kt = 0; kt < 8; kt++) {
                unsigned b[2] = {w[2 * kt], w[2 * kt + 1]};
                mma_tf32(s[nt], qa[kt], b);
            }
        }

        // ---- Online softmax (rows g and g+8) ----
        #pragma unroll
        for (int half = 0; half < 2; half++) {
            const int c0 = half * 2, c1 = half * 2 + 1;
            float rmax = -INFINITY;
            #pragma unroll
            for (int nt = 0; nt < 8; nt++)
                rmax = fmaxf(rmax, fmaxf(s[nt][c0], s[nt][c1]));
            rmax = fmaxf(rmax, __shfl_xor_sync(0xffffffffu, rmax, 1));
            rmax = fmaxf(rmax, __shfl_xor_sync(0xffffffffu, rmax, 2));
            float mn = fmaxf(mrow[half], rmax);
            float alpha = __expf(mrow[half] - mn);
            mrow[half] = mn;
            float rs = 0.f;
            #pragma unroll
            for (int nt = 0; nt < 8; nt++) {
                float p0 = __expf(s[nt][c0] - mn);
                float p1 = __expf(s[nt][c1] - mn);
                s[nt][c0] = p0; s[nt][c1] = p1;
                rs += p0 + p1;
            }
            rs += __shfl_xor_sync(0xffffffffu, rs, 1);
            rs += __shfl_xor_sync(0xffffffffu, rs, 2);
            lrow[half] = lrow[half] * alpha + rs;
            #pragma unroll
            for (int nt = 0; nt < 8; nt++) {
                o[nt][c0] *= alpha;
                o[nt][c1] *= alpha;
            }
        }

        // ---- P -> QB (c-frag scatter), re-read as A-frags ----
        {
            int cc = (2 * r) & 3;            // 0 or 2
            int jb = r >> 1;                 // 0 or 1
            unsigned* plo = &QB[wbase + g * 84 + cc * 20 + jb];
            unsigned* phi = &QB[wbase + (g + 8) * 84 + cc * 20 + jb];
            #pragma unroll
            for (int nt = 0; nt < 8; nt++) {
                plo[2 * nt]      = f2tf(s[nt][0]);
                plo[2 * nt + 20] = f2tf(s[nt][1]);
                phi[2 * nt]      = f2tf(s[nt][2]);
                phi[2 * nt + 20] = f2tf(s[nt][3]);
            }
        }
        __syncwarp();

        unsigned pa[8][4];
        {
            const uint4* lo4 = reinterpret_cast<const uint4*>(&QB[wbase + g * 84 + r * 20]);
            const uint4* hi4 = reinterpret_cast<const uint4*>(&QB[wbase + (g + 8) * 84 + r * 20]);
            uint4 L[4] = {lo4[0], lo4[1], lo4[2], lo4[3]};
            uint4 H[4] = {hi4[0], hi4[1], hi4[2], hi4[3]};
            const unsigned* lo = reinterpret_cast<const unsigned*>(L);
            const unsigned* hi = reinterpret_cast<const unsigned*>(H);
            #pragma unroll
            for (int kt = 0; kt < 8; kt++) {
                pa[kt][0] = lo[2 * kt];
                pa[kt][1] = hi[2 * kt];
                pa[kt][2] = lo[2 * kt + 1];
                pa[kt][3] = hi[2 * kt + 1];
            }
        }

        // ---- O += P @ V ----
        #pragma unroll
        for (int kt = 0; kt < 8; kt++) {
            const uint4* va4 = reinterpret_cast<const uint4*>(
                &VB[(8 * kt + r) * 104 + g * 12]);
            const uint4* vb4 = reinterpret_cast<const uint4*>(
                &VB[(8 * kt + r + 4) * 104 + g * 12]);
            uint4 A0 = va4[0], A1 = va4[1], B0 = vb4[0], B1 = vb4[1];
            const unsigned* wa = reinterpret_cast<const unsigned*>(&A0);
            unsigned waa[8] = {A0.x, A0.y, A0.z, A0.w, A1.x, A1.y, A1.z, A1.w};
            unsigned wbb[8] = {B0.x, B0.y, B0.z, B0.w, B1.x, B1.y, B1.z, B1.w};
            (void)wa;
            #pragma unroll
            for (int nt = 0; nt < 8; nt++) {
                unsigned b[2] = {waa[nt], wbb[nt]};
                mma_tf32(o[nt], pa[kt], b);
            }
        }
        __syncthreads();   // before KB/VB overwrite next tile
    }

    // ---- Normalize and write ctx ----
    float inv0 = 1.0f / lrow[0], inv1 = 1.0f / lrow[1];
    const int qb = warp * 16;
    #pragma unroll
    for (int nt = 0; nt < 8; nt++) {
        int col = h * HD + nt * 8 + 2 * r;
        float2 v0 = make_float2(o[nt][0] * inv0, o[nt][1] * inv0);
        float2 v1 = make_float2(o[nt][2] * inv1, o[nt][3] * inv1);
        *reinterpret_cast<float2*>(&ctx[(long)(i0 + qb + g)     * DM + col]) = v0;
        *reinterpret_cast<float2*>(&ctx[(long)(i0 + qb + g + 8) * DM + col]) = v1;
    }
}

// --------------------------------------------------------------------------
// Launcher
// --------------------------------------------------------------------------
extern "C" void kernel_launch(void* const* d_in, const int* in_sizes, int n_in,
                              void* d_out, int out_size)
{
    const float* X    = (const float*)d_in[0];
    const float* Wq   = (const float*)d_in[1];
    const float* Wdkv = (const float*)d_in[2];
    const float* Wuk  = (const float*)d_in[3];
    const float* Wuv  = (const float*)d_in[4];
    const float* Wo   = (const float*)d_in[5];
    const float* wW   = (const float*)d_in[6];
    const float* wb   = (const float*)d_in[7];
    float* out = (float*)d_out;

    float *q, *ckv, *kk, *vv, *ctx;
    cudaGetSymbolAddress((void**)&q,   g_q);
    cudaGetSymbolAddress((void**)&ckv, g_ckv);
    cudaGetSymbolAddress((void**)&kk,  g_k);
    cudaGetSymbolAddress((void**)&vv,  g_v);
    cudaGetSymbolAddress((void**)&ctx, g_ctx);

    gemm_tc<<<dim3(DM / 128, SEQ / 128, 1), 256>>>(X, Wq, nullptr, q,
                                                   SEQ, DM, DM, DM, DM, DM);
    gemm_tc<<<dim3(LAT / 128, SEQ / 128, 1), 256>>>(X, Wdkv, nullptr, ckv,
                                                    SEQ, LAT, DM, DM, LAT, LAT);
    gemm_tc<<<dim3(DM / 128, SEQ / 128, 1), 256>>>(ckv, Wuk, nullptr, kk,
                                                   SEQ, DM, LAT, LAT, DM, DM);
    gemm_tc<<<dim3(DM / 128, SEQ / 128, 1), 256>>>(ckv, Wuv, nullptr, vv,
                                                   SEQ, DM, LAT, LAT, DM, DM);

    const int smem = 22528 * (int)sizeof(unsigned);  // 90112 B
    cudaFuncSetAttribute(flash_tc2, cudaFuncAttributeMaxDynamicSharedMemorySize, smem);
    flash_tc2<<<dim3(SEQ / 128, NH, 1), 256, smem>>>(q, kk, vv, ctx);

    gemm_tc<<<dim3(DM / 128, SEQ / 128, 1), 256>>>(ctx, Wo, nullptr, out,
                                                   SEQ, DM, DM, DM, DM, 2048);
    gemm_tc<<<dim3(256 / 128, SEQ / 128, 4), 256>>>(out, wW, wb, out + 1024,
                                                    SEQ, 256, DM, 2048, 256, 2048);
}